// round 15
// baseline (speedup 1.0000x reference)
#include <cuda_runtime.h>
#include <cstdint>
#include <math.h>

#define RANGE_MIN (-5.0f)
#define RANGE_MAX (5.0f)
#define MIN_BIN_SIZE 0.0001f
#define MIN_SLOPE 0.0001f
#define KBINS 8

// smem table layout (built per block, hidden under input-load latency):
//  per bin b, stride 12 (48B => conflict-free dual LDS.128):
//   [b*12+0..3] = nxkw(-x_k*inv_w), inv_w, y_k, A(=h*(s-dk))
//   [b*12+4..7] = B(=h*dk), cc(=dk+dk1-2s), s, dk
//  [96..102] interior knots x_pos[1..7]
//  [103] = d0 (left edge slope), [104] = d8 (right edge slope)

// Warp-parallel prep: ALL 32 lanes call this (no divergent shuffles).
// Lanes 0-15: softmax exps (group max via width-8 butterflies, executed by
// every lane uniformly; only lanes 0-15 use the result). Lanes 16-24: softplus.
// Lane 0: cheap serial algebra via smem scratch.
__device__ __forceinline__ void prep_warp(const float* __restrict__ p,
                                          float* __restrict__ stab,
                                          float* __restrict__ se,
                                          float* __restrict__ sxp,
                                          float* __restrict__ syp,
                                          int lane) {
    float pv = (lane < 25) ? __ldg(&p[lane]) : 0.f;

    // uniform (non-divergent) butterfly group-max, width 8
    float m = pv;
    m = fmaxf(m, __shfl_xor_sync(0xffffffffu, m, 1, 8));
    m = fmaxf(m, __shfl_xor_sync(0xffffffffu, m, 2, 8));
    m = fmaxf(m, __shfl_xor_sync(0xffffffffu, m, 4, 8));

    float e;
    if (lane < 16) {
        e = __expf(pv - m);
    } else {
        const float off = 0.54130250f;  // logf(expf(1-1e-4f)-1)
        float z = pv + off;
        e = __logf(1.0f + __expf(z)) + MIN_SLOPE;
    }
    if (lane < 25) se[lane] = e;
    __syncwarp();

    if (lane == 0) {
        float sw = 0.f, sh = 0.f;
        #pragma unroll
        for (int i = 0; i < 8; i++) { sw += se[i]; sh += se[8 + i]; }
        const float scale = (RANGE_MAX - RANGE_MIN) - KBINS * MIN_BIN_SIZE;
        float isw = scale / sw, ish = scale / sh;

        sxp[0] = RANGE_MIN; syp[0] = RANGE_MIN;
        float cx = 0.f, cy = 0.f;
        #pragma unroll
        for (int i = 0; i < 8; i++) {
            cx += se[i]     * isw + MIN_BIN_SIZE; sxp[i + 1] = RANGE_MIN + cx;
            cy += se[8 + i] * ish + MIN_BIN_SIZE; syp[i + 1] = RANGE_MIN + cy;
        }
        #pragma unroll
        for (int b = 0; b < KBINS; b++) {
            float wid   = sxp[b + 1] - sxp[b];
            float hei   = syp[b + 1] - syp[b];
            float inv_w = 1.0f / wid;
            float s     = hei * inv_w;
            float dk    = se[16 + b];
            float dk1   = se[17 + b];
            stab[b * 12 + 0] = -sxp[b] * inv_w;
            stab[b * 12 + 1] = inv_w;
            stab[b * 12 + 2] = syp[b];
            stab[b * 12 + 3] = hei * (s - dk);       // A
            stab[b * 12 + 4] = hei * dk;             // B
            stab[b * 12 + 5] = dk1 + dk - 2.0f * s;  // cc
            stab[b * 12 + 6] = s;
            stab[b * 12 + 7] = dk;
        }
        #pragma unroll
        for (int i = 0; i < 7; i++) stab[96 + i] = sxp[1 + i];
        stab[103] = se[16];
        stab[104] = se[24];
    }
}

__device__ __forceinline__ void rqs_eval(float xx, const float* __restrict__ stab,
                                         float k1, float k2, float k3, float k4,
                                         float k5, float k6, float k7,
                                         float d0, float d8,
                                         float& y_out, float& ld_out) {
    float xc = fminf(fmaxf(xx, RANGE_MIN), RANGE_MAX);

    // binary searchsorted over 7 interior knots (side='right'); oA = bin*48 bytes
    bool  c2  = xc >= k4;
    float km1 = c2 ? k6 : k2;
    bool  c1  = xc >= km1;
    float kmA = c2 ? k7 : k3;
    float kmB = c2 ? k5 : k1;
    float km0 = c1 ? kmA : kmB;
    bool  c0  = xc >= km0;
    int oA = (c2 ? 192 : 0) + (c1 ? 96 : 0) + (c0 ? 48 : 0);

    const float* bp = (const float*)((const char*)stab + oA);
    const float4 lo = *reinterpret_cast<const float4*>(bp);      // nxkw, inv_w, y_k, A
    const float4 hi = *reinterpret_cast<const float4*>(bp + 4);  // B, cc, s, dk

    float xi = fmaf(xc, lo.y, lo.x);

    float B = hi.x, cc = hi.y, s = hi.z, dk = hi.w;

    // y = y_k + xi*(A*xi + B) / den,  den = (-cc)*xi^2 + cc*xi + s
    float num = xi * fmaf(lo.w, xi, B);
    float den = fmaf(fmaf(-cc, xi, cc), xi, s);
    float r   = __fdividef(1.0f, den);
    float y   = fmaf(num, r, lo.z);

    // linear tail (0 in-range); edge slopes are global scalars d0/d8
    float edge = (xx < 0.0f) ? d0 : d8;
    y = fmaf(xx - xc, edge, y);

    // inner = cc*xi^2 + 2(s-dk)*xi + dk ; deriv = (s*r)^2 * inner
    float F  = s - dk;
    float inner = fmaf(fmaf(cc, xi, F + F), xi, dk);
    float srr = s * r;
    ld_out = __logf(srr * srr * inner);   // == log(d0)/log(d8) at clamped bounds
    y_out  = y;
}

// Single fused kernel: 4 LDG.128 issued first, warp-0 prep hidden under their
// latency, then Horner-form spline with conflict-free smem gathers.
__global__ void __launch_bounds__(256, 5) rqs_main_kernel(
    const float* __restrict__ p,
    const float4* __restrict__ x4,
    float4* __restrict__ y4,
    float4* __restrict__ ld4
) {
    __shared__ __align__(16) float stab[112];
    __shared__ float se[25];
    __shared__ float sxp[9], syp[9];

    const int tid = threadIdx.x;
    const int i0  = blockIdx.x * 1024 + tid;

    // all input loads issued up front — 4 outstanding LDG.128 per thread,
    // independent of the prep below (scoreboard waits land at first use).
    float4 xv0 = __ldcs(&x4[i0]);
    float4 xv1 = __ldcs(&x4[i0 + 256]);
    float4 xv2 = __ldcs(&x4[i0 + 512]);
    float4 xv3 = __ldcs(&x4[i0 + 768]);

    if (tid < 32) prep_warp(p, stab, se, sxp, syp, tid);
    __syncthreads();

    const float k1 = stab[96],  k2 = stab[97],  k3 = stab[98],  k4 = stab[99];
    const float k5 = stab[100], k6 = stab[101], k7 = stab[102];
    const float d0 = stab[103], d8 = stab[104];

    float4 yv, lv;

    rqs_eval(xv0.x, stab, k1,k2,k3,k4,k5,k6,k7, d0,d8, yv.x, lv.x);
    rqs_eval(xv0.y, stab, k1,k2,k3,k4,k5,k6,k7, d0,d8, yv.y, lv.y);
    rqs_eval(xv0.z, stab, k1,k2,k3,k4,k5,k6,k7, d0,d8, yv.z, lv.z);
    rqs_eval(xv0.w, stab, k1,k2,k3,k4,k5,k6,k7, d0,d8, yv.w, lv.w);
    __stcs(&y4[i0],  yv);
    __stcs(&ld4[i0], lv);

    rqs_eval(xv1.x, stab, k1,k2,k3,k4,k5,k6,k7, d0,d8, yv.x, lv.x);
    rqs_eval(xv1.y, stab, k1,k2,k3,k4,k5,k6,k7, d0,d8, yv.y, lv.y);
    rqs_eval(xv1.z, stab, k1,k2,k3,k4,k5,k6,k7, d0,d8, yv.z, lv.z);
    rqs_eval(xv1.w, stab, k1,k2,k3,k4,k5,k6,k7, d0,d8, yv.w, lv.w);
    __stcs(&y4[i0 + 256],  yv);
    __stcs(&ld4[i0 + 256], lv);

    rqs_eval(xv2.x, stab, k1,k2,k3,k4,k5,k6,k7, d0,d8, yv.x, lv.x);
    rqs_eval(xv2.y, stab, k1,k2,k3,k4,k5,k6,k7, d0,d8, yv.y, lv.y);
    rqs_eval(xv2.z, stab, k1,k2,k3,k4,k5,k6,k7, d0,d8, yv.z, lv.z);
    rqs_eval(xv2.w, stab, k1,k2,k3,k4,k5,k6,k7, d0,d8, yv.w, lv.w);
    __stcs(&y4[i0 + 512],  yv);
    __stcs(&ld4[i0 + 512], lv);

    rqs_eval(xv3.x, stab, k1,k2,k3,k4,k5,k6,k7, d0,d8, yv.x, lv.x);
    rqs_eval(xv3.y, stab, k1,k2,k3,k4,k5,k6,k7, d0,d8, yv.y, lv.y);
    rqs_eval(xv3.z, stab, k1,k2,k3,k4,k5,k6,k7, d0,d8, yv.z, lv.z);
    rqs_eval(xv3.w, stab, k1,k2,k3,k4,k5,k6,k7, d0,d8, yv.w, lv.w);
    __stcs(&y4[i0 + 768],  yv);
    __stcs(&ld4[i0 + 768], lv);
}

// Tail: handles [start, n) scalar-wise (not launched when n % 4096 == 0)
__global__ void rqs_tail_kernel(const float* __restrict__ p,
                                const float* __restrict__ x,
                                float* __restrict__ y,
                                float* __restrict__ ld,
                                int start, int n) {
    __shared__ __align__(16) float stab[112];
    __shared__ float se[25];
    __shared__ float sxp[9], syp[9];
    if (threadIdx.x < 32) prep_warp(p, stab, se, sxp, syp, threadIdx.x);
    __syncthreads();
    for (int idx = start + blockIdx.x * blockDim.x + threadIdx.x; idx < n;
         idx += gridDim.x * blockDim.x) {
        float yy, ll;
        rqs_eval(x[idx], stab,
                 stab[96], stab[97], stab[98], stab[99],
                 stab[100], stab[101], stab[102],
                 stab[103], stab[104], yy, ll);
        y[idx]  = yy;
        ld[idx] = ll;
    }
}

extern "C" void kernel_launch(void* const* d_in, const int* in_sizes, int n_in,
                              void* d_out, int out_size) {
    const float* x = (const float*)d_in[0];
    const float* p = (const float*)d_in[1];
    float* out = (float*)d_out;
    const int n = in_sizes[0];

    float* y_ptr  = out;       // out[0:N]  = y
    float* ld_ptr = out + n;   // out[N:2N] = logdet

    const int elems_per_block = 4096;            // 256 thr * 4 * float4
    const int full_blocks = n / elems_per_block; // exact tiles, no bounds checks
    if (full_blocks > 0) {
        rqs_main_kernel<<<full_blocks, 256>>>(
            p, (const float4*)x, (float4*)y_ptr, (float4*)ld_ptr);
    }
    const int done = full_blocks * elems_per_block;
    if (done < n) {
        rqs_tail_kernel<<<4, 256>>>(p, x, y_ptr, ld_ptr, done, n);
    }
}

// round 16
// speedup vs baseline: 1.0970x; 1.0970x over previous
#include <cuda_runtime.h>
#include <cstdint>
#include <math.h>

#define RANGE_MIN (-5.0f)
#define RANGE_MAX (5.0f)
#define MIN_BIN_SIZE 0.0001f
#define MIN_SLOPE 0.0001f
#define KBINS 8

// Global blob (112 floats):
//  per bin b, stride 12 (48B => conflict-free dual LDS.128):
//   [b*12+0..3] = nxkw(-x_k*inv_w), inv_w, y_k, A(=h*(s-dk))
//   [b*12+4..7] = B(=h*dk), cc(=dk+dk1-2s), s, dk
//  [96..102] interior knots x_pos[1..7]
//  [103] = d0 (left edge slope), [104] = d8 (right edge slope)
__device__ __align__(16) float g_small[112];

// Parallel prep: lanes 0-7 width exps, 8-15 height exps, 16-24 softplus slopes;
// lane 0 finishes with the cheap serial algebra (sums/cumsums/table writes).
__global__ void rqs_prep_kernel(const float* __restrict__ p) {
    __shared__ float sp[25];
    __shared__ float se[25];   // exps / softplus results
    const int t = threadIdx.x;

    if (t < 25) sp[t] = p[t];
    __syncwarp();

    if (t < 8) {
        float mw = sp[0];
        #pragma unroll
        for (int i = 1; i < 8; i++) mw = fmaxf(mw, sp[i]);
        se[t] = __expf(sp[t] - mw);
    } else if (t < 16) {
        float mh = sp[8];
        #pragma unroll
        for (int i = 9; i < 16; i++) mh = fmaxf(mh, sp[i]);
        se[t] = __expf(sp[t] - mh);
    } else if (t < 25) {
        const float off = 0.54130250f;  // logf(expf(1.0f - 1e-4f) - 1.0f)
        float z = sp[t] + off;
        se[t] = __logf(1.0f + __expf(z)) + MIN_SLOPE;
    }
    __syncwarp();

    if (t == 0) {
        float sw = 0.f, sh = 0.f;
        #pragma unroll
        for (int i = 0; i < 8; i++) { sw += se[i]; sh += se[8 + i]; }
        const float total = RANGE_MAX - RANGE_MIN;
        const float scale = total - KBINS * MIN_BIN_SIZE;
        float isw = scale / sw, ish = scale / sh;

        float xp[KBINS + 1], yp[KBINS + 1];
        xp[0] = RANGE_MIN; yp[0] = RANGE_MIN;
        float cx = 0.f, cy = 0.f;
        #pragma unroll
        for (int i = 0; i < 8; i++) {
            cx += se[i]     * isw + MIN_BIN_SIZE; xp[i + 1] = RANGE_MIN + cx;
            cy += se[8 + i] * ish + MIN_BIN_SIZE; yp[i + 1] = RANGE_MIN + cy;
        }
        #pragma unroll
        for (int b = 0; b < KBINS; b++) {
            float wid   = xp[b + 1] - xp[b];
            float hei   = yp[b + 1] - yp[b];
            float inv_w = 1.0f / wid;
            float s     = hei * inv_w;
            float dk    = se[16 + b];
            float dk1   = se[17 + b];
            g_small[b * 12 + 0]  = -xp[b] * inv_w;
            g_small[b * 12 + 1]  = inv_w;
            g_small[b * 12 + 2]  = yp[b];
            g_small[b * 12 + 3]  = hei * (s - dk);       // A
            g_small[b * 12 + 4]  = hei * dk;             // B
            g_small[b * 12 + 5]  = dk1 + dk - 2.0f * s;  // cc
            g_small[b * 12 + 6]  = s;
            g_small[b * 12 + 7]  = dk;
            g_small[b * 12 + 8]  = 0.f;
            g_small[b * 12 + 9]  = 0.f;
            g_small[b * 12 + 10] = 0.f;
            g_small[b * 12 + 11] = 0.f;
        }
        #pragma unroll
        for (int i = 0; i < 7; i++) g_small[96 + i] = xp[1 + i];
        g_small[103] = se[16];
        g_small[104] = se[24];
        g_small[105] = 0.f; g_small[106] = 0.f; g_small[107] = 0.f;
        g_small[108] = 0.f; g_small[109] = 0.f; g_small[110] = 0.f;
        g_small[111] = 0.f;
    }
}

__device__ __forceinline__ void rqs_eval(float xx, const float* __restrict__ stab,
                                         float k1, float k2, float k3, float k4,
                                         float k5, float k6, float k7,
                                         float d0, float d8,
                                         float& y_out, float& ld_out) {
    float xc = fminf(fmaxf(xx, RANGE_MIN), RANGE_MAX);

    // binary searchsorted over 7 interior knots (side='right'); oA = bin*48 bytes
    bool  c2  = xc >= k4;
    float km1 = c2 ? k6 : k2;
    bool  c1  = xc >= km1;
    float kmA = c2 ? k7 : k3;
    float kmB = c2 ? k5 : k1;
    float km0 = c1 ? kmA : kmB;
    bool  c0  = xc >= km0;
    int oA = (c2 ? 192 : 0) + (c1 ? 96 : 0) + (c0 ? 48 : 0);

    const float* bp = (const float*)((const char*)stab + oA);
    const float4 lo = *reinterpret_cast<const float4*>(bp);      // nxkw, inv_w, y_k, A
    const float4 hi = *reinterpret_cast<const float4*>(bp + 4);  // B, cc, s, dk

    float xi = fmaf(xc, lo.y, lo.x);

    float B = hi.x, cc = hi.y, s = hi.z, dk = hi.w;

    // y = y_k + xi*(A*xi + B) / den,  den = (-cc)*xi^2 + cc*xi + s
    float num = xi * fmaf(lo.w, xi, B);
    float den = fmaf(fmaf(-cc, xi, cc), xi, s);
    float r   = __fdividef(1.0f, den);
    float y   = fmaf(num, r, lo.z);

    // linear tail (0 in-range); edge slopes are global scalars d0/d8
    float edge = (xx < 0.0f) ? d0 : d8;
    y = fmaf(xx - xc, edge, y);

    // inner = cc*xi^2 + 2(s-dk)*xi + dk ; deriv = (s*r)^2 * inner
    float F  = s - dk;
    float inner = fmaf(fmaf(cc, xi, F + F), xi, dk);
    float srr = s * r;
    ld_out = __logf(srr * srr * inner);   // == log(d0)/log(d8) at clamped bounds
    y_out  = y;
}

// MLP=8: all 8 LDG.128 issued up front (~32KB in flight per SM at 32 warps),
// then per-float4 eval+store. launch_bounds(256,4) => 64-reg budget.
__global__ void __launch_bounds__(256, 4) rqs_main_kernel(
    const float4* __restrict__ x4,
    float4* __restrict__ y4,
    float4* __restrict__ ld4
) {
    __shared__ __align__(16) float smem[112];
    if (threadIdx.x < 112) smem[threadIdx.x] = g_small[threadIdx.x];
    __syncthreads();

    const float k1 = smem[96],  k2 = smem[97],  k3 = smem[98],  k4 = smem[99];
    const float k5 = smem[100], k6 = smem[101], k7 = smem[102];
    const float d0 = smem[103], d8 = smem[104];

    const int tid = threadIdx.x;
    const int i0  = blockIdx.x * 2048 + tid;

    // all 8 input loads issued up front
    float4 xv0 = __ldcs(&x4[i0]);
    float4 xv1 = __ldcs(&x4[i0 + 256]);
    float4 xv2 = __ldcs(&x4[i0 + 512]);
    float4 xv3 = __ldcs(&x4[i0 + 768]);
    float4 xv4 = __ldcs(&x4[i0 + 1024]);
    float4 xv5 = __ldcs(&x4[i0 + 1280]);
    float4 xv6 = __ldcs(&x4[i0 + 1536]);
    float4 xv7 = __ldcs(&x4[i0 + 1792]);

    float4 yv, lv;

#define EVAL4(XV, OFF)                                                     \
    rqs_eval(XV.x, smem, k1,k2,k3,k4,k5,k6,k7, d0,d8, yv.x, lv.x);         \
    rqs_eval(XV.y, smem, k1,k2,k3,k4,k5,k6,k7, d0,d8, yv.y, lv.y);         \
    rqs_eval(XV.z, smem, k1,k2,k3,k4,k5,k6,k7, d0,d8, yv.z, lv.z);         \
    rqs_eval(XV.w, smem, k1,k2,k3,k4,k5,k6,k7, d0,d8, yv.w, lv.w);         \
    __stcs(&y4[i0 + (OFF)],  yv);                                          \
    __stcs(&ld4[i0 + (OFF)], lv);

    EVAL4(xv0, 0)
    EVAL4(xv1, 256)
    EVAL4(xv2, 512)
    EVAL4(xv3, 768)
    EVAL4(xv4, 1024)
    EVAL4(xv5, 1280)
    EVAL4(xv6, 1536)
    EVAL4(xv7, 1792)
#undef EVAL4
}

// Tail: handles [start, n) scalar-wise (not launched when n % 8192 == 0)
__global__ void rqs_tail_kernel(const float* __restrict__ x,
                                float* __restrict__ y,
                                float* __restrict__ ld,
                                int start, int n) {
    __shared__ __align__(16) float smem[112];
    if (threadIdx.x < 112) smem[threadIdx.x] = g_small[threadIdx.x];
    __syncthreads();
    for (int idx = start + blockIdx.x * blockDim.x + threadIdx.x; idx < n;
         idx += gridDim.x * blockDim.x) {
        float yy, ll;
        rqs_eval(x[idx], smem,
                 smem[96], smem[97], smem[98], smem[99],
                 smem[100], smem[101], smem[102],
                 smem[103], smem[104], yy, ll);
        y[idx]  = yy;
        ld[idx] = ll;
    }
}

extern "C" void kernel_launch(void* const* d_in, const int* in_sizes, int n_in,
                              void* d_out, int out_size) {
    const float* x = (const float*)d_in[0];
    const float* p = (const float*)d_in[1];
    float* out = (float*)d_out;
    const int n = in_sizes[0];

    float* y_ptr  = out;       // out[0:N]  = y
    float* ld_ptr = out + n;   // out[N:2N] = logdet

    rqs_prep_kernel<<<1, 32>>>(p);

    const int elems_per_block = 8192;            // 256 thr * 8 * float4
    const int full_blocks = n / elems_per_block; // exact tiles, no bounds checks
    if (full_blocks > 0) {
        rqs_main_kernel<<<full_blocks, 256>>>(
            (const float4*)x, (float4*)y_ptr, (float4*)ld_ptr);
    }
    const int done = full_blocks * elems_per_block;
    if (done < n) {
        rqs_tail_kernel<<<8, 256>>>(x, y_ptr, ld_ptr, done, n);
    }
}

// round 17
// speedup vs baseline: 1.0975x; 1.0005x over previous
#include <cuda_runtime.h>
#include <cstdint>
#include <math.h>

#define RANGE_MIN (-5.0f)
#define RANGE_MAX (5.0f)
#define MIN_BIN_SIZE 0.0001f
#define MIN_SLOPE 0.0001f
#define KBINS 8

// Global blob (112 floats):
//  per bin b, stride 12 (48B => conflict-free dual LDS.128):
//   [b*12+0..3] = nxkw(-x_k*inv_w), inv_w, y_k, h
//   [b*12+4..7] = cc(=dk+dk1-2s), s, dk, ew(=wid*d0 | wid*d8 | 0)
//  [96..102] interior knots x_pos[1..7]
__device__ __align__(16) float g_small[112];

// Parallel prep: lanes 0-7 width exps, 8-15 height exps, 16-24 softplus slopes;
// lane 0 finishes with the cheap serial algebra. Triggers PDL completion early.
__global__ void rqs_prep_kernel(const float* __restrict__ p) {
    __shared__ float sp[25];
    __shared__ float se[25];
    const int t = threadIdx.x;

    if (t < 25) sp[t] = p[t];
    __syncwarp();

    if (t < 8) {
        float mw = sp[0];
        #pragma unroll
        for (int i = 1; i < 8; i++) mw = fmaxf(mw, sp[i]);
        se[t] = __expf(sp[t] - mw);
    } else if (t < 16) {
        float mh = sp[8];
        #pragma unroll
        for (int i = 9; i < 16; i++) mh = fmaxf(mh, sp[i]);
        se[t] = __expf(sp[t] - mh);
    } else if (t < 25) {
        const float off = 0.54130250f;  // logf(expf(1.0f - 1e-4f) - 1.0f)
        float z = sp[t] + off;
        se[t] = __logf(1.0f + __expf(z)) + MIN_SLOPE;
    }
    __syncwarp();

    if (t == 0) {
        float sw = 0.f, sh = 0.f;
        #pragma unroll
        for (int i = 0; i < 8; i++) { sw += se[i]; sh += se[8 + i]; }
        const float scale = (RANGE_MAX - RANGE_MIN) - KBINS * MIN_BIN_SIZE;
        float isw = scale / sw, ish = scale / sh;

        float xp[KBINS + 1], yp[KBINS + 1];
        xp[0] = RANGE_MIN; yp[0] = RANGE_MIN;
        float cx = 0.f, cy = 0.f;
        #pragma unroll
        for (int i = 0; i < 8; i++) {
            cx += se[i]     * isw + MIN_BIN_SIZE; xp[i + 1] = RANGE_MIN + cx;
            cy += se[8 + i] * ish + MIN_BIN_SIZE; yp[i + 1] = RANGE_MIN + cy;
        }
        #pragma unroll
        for (int b = 0; b < KBINS; b++) {
            float wid   = xp[b + 1] - xp[b];
            float hei   = yp[b + 1] - yp[b];
            float inv_w = 1.0f / wid;
            float s     = hei * inv_w;
            float dk    = se[16 + b];
            float dk1   = se[17 + b];
            float ew    = (b == 0) ? wid * se[16]
                        : ((b == KBINS - 1) ? wid * se[24] : 0.0f);
            g_small[b * 12 + 0]  = -xp[b] * inv_w;
            g_small[b * 12 + 1]  = inv_w;
            g_small[b * 12 + 2]  = yp[b];
            g_small[b * 12 + 3]  = hei;
            g_small[b * 12 + 4]  = dk1 + dk - 2.0f * s;  // cc
            g_small[b * 12 + 5]  = s;
            g_small[b * 12 + 6]  = dk;
            g_small[b * 12 + 7]  = ew;
            g_small[b * 12 + 8]  = 0.f;
            g_small[b * 12 + 9]  = 0.f;
            g_small[b * 12 + 10] = 0.f;
            g_small[b * 12 + 11] = 0.f;
        }
        #pragma unroll
        for (int i = 0; i < 7; i++) g_small[96 + i] = xp[1 + i];
        #pragma unroll
        for (int i = 103; i < 112; i++) g_small[i] = 0.f;
        __threadfence();
    }
    __syncwarp();
#if __CUDA_ARCH__ >= 900
    cudaTriggerProgrammaticLaunchCompletion();
#endif
}

__device__ __forceinline__ void rqs_eval(float xx, const float* __restrict__ stab,
                                         float k1, float k2, float k3, float k4,
                                         float k5, float k6, float k7,
                                         float& y_out, float& ld_out) {
    // binary searchsorted over 7 interior knots on RAW x (side='right');
    // out-of-range lands in bin 0 / bin 7 naturally.
    bool  c2  = xx >= k4;
    float km1 = c2 ? k6 : k2;
    bool  c1  = xx >= km1;
    float kmA = c2 ? k7 : k3;
    float kmB = c2 ? k5 : k1;
    float km0 = c1 ? kmA : kmB;
    bool  c0  = xx >= km0;
    int oA = (c2 ? 192 : 0) + (c1 ? 96 : 0) + (c0 ? 48 : 0);

    const float* bp = (const float*)((const char*)stab + oA);
    const float4 lo = *reinterpret_cast<const float4*>(bp);      // nxkw, inv_w, y_k, h
    const float4 hi = *reinterpret_cast<const float4*>(bp + 4);  // cc, s, dk, ew

    float cc = hi.x, s = hi.y, dk = hi.z, ew = hi.w;

    float xi_un = fmaf(xx, lo.y, lo.x);           // (x - x_k) * inv_w, unclamped
    float xi    = fminf(fmaxf(xi_un, 0.0f), 1.0f);
    float dxi   = xi_un - xi;                     // 0 in-range

    float F = s - dk;
    float A = lo.w * F;                           // h*(s-dk)
    float B = lo.w * dk;                          // h*dk

    // y = y_k + xi*(A*xi + B)/den + dxi*ew,  den = (-cc)*xi^2 + cc*xi + s
    float num = xi * fmaf(A, xi, B);
    float den = fmaf(fmaf(-cc, xi, cc), xi, s);
    float r   = __fdividef(1.0f, den);
    float y   = fmaf(num, r, lo.z);
    y = fmaf(dxi, ew, y);                         // linear tail (ew=0 for bins 1-6)

    // inner = cc*xi^2 + 2F*xi + dk ; deriv = (s*r)^2 * inner
    float inner = fmaf(fmaf(cc, xi, F + F), xi, dk);
    float srr = s * r;
    ld_out = __logf(srr * srr * inner);           // == log(d0)/log(d8) at bounds
    y_out  = y;
}

// MLP=4 up-front loads; PDL gridsync placed AFTER the input loads so main's
// launch + first LDG latency overlap the prep kernel.
__global__ void __launch_bounds__(256, 5) rqs_main_kernel(
    const float4* __restrict__ x4,
    float4* __restrict__ y4,
    float4* __restrict__ ld4
) {
    __shared__ __align__(16) float smem[112];

    const int tid = threadIdx.x;
    const int i0  = blockIdx.x * 1024 + tid;

    // all input loads issued up front — independent of prep results
    float4 xv0 = __ldcs(&x4[i0]);
    float4 xv1 = __ldcs(&x4[i0 + 256]);
    float4 xv2 = __ldcs(&x4[i0 + 512]);
    float4 xv3 = __ldcs(&x4[i0 + 768]);

#if __CUDA_ARCH__ >= 900
    cudaGridDependencySynchronize();
#endif

    if (tid < 112) smem[tid] = g_small[tid];
    __syncthreads();

    const float k1 = smem[96],  k2 = smem[97],  k3 = smem[98],  k4 = smem[99];
    const float k5 = smem[100], k6 = smem[101], k7 = smem[102];

    float4 yv, lv;

    rqs_eval(xv0.x, smem, k1,k2,k3,k4,k5,k6,k7, yv.x, lv.x);
    rqs_eval(xv0.y, smem, k1,k2,k3,k4,k5,k6,k7, yv.y, lv.y);
    rqs_eval(xv0.z, smem, k1,k2,k3,k4,k5,k6,k7, yv.z, lv.z);
    rqs_eval(xv0.w, smem, k1,k2,k3,k4,k5,k6,k7, yv.w, lv.w);
    __stcs(&y4[i0],  yv);
    __stcs(&ld4[i0], lv);

    rqs_eval(xv1.x, smem, k1,k2,k3,k4,k5,k6,k7, yv.x, lv.x);
    rqs_eval(xv1.y, smem, k1,k2,k3,k4,k5,k6,k7, yv.y, lv.y);
    rqs_eval(xv1.z, smem, k1,k2,k3,k4,k5,k6,k7, yv.z, lv.z);
    rqs_eval(xv1.w, smem, k1,k2,k3,k4,k5,k6,k7, yv.w, lv.w);
    __stcs(&y4[i0 + 256],  yv);
    __stcs(&ld4[i0 + 256], lv);

    rqs_eval(xv2.x, smem, k1,k2,k3,k4,k5,k6,k7, yv.x, lv.x);
    rqs_eval(xv2.y, smem, k1,k2,k3,k4,k5,k6,k7, yv.y, lv.y);
    rqs_eval(xv2.z, smem, k1,k2,k3,k4,k5,k6,k7, yv.z, lv.z);
    rqs_eval(xv2.w, smem, k1,k2,k3,k4,k5,k6,k7, yv.w, lv.w);
    __stcs(&y4[i0 + 512],  yv);
    __stcs(&ld4[i0 + 512], lv);

    rqs_eval(xv3.x, smem, k1,k2,k3,k4,k5,k6,k7, yv.x, lv.x);
    rqs_eval(xv3.y, smem, k1,k2,k3,k4,k5,k6,k7, yv.y, lv.y);
    rqs_eval(xv3.z, smem, k1,k2,k3,k4,k5,k6,k7, yv.z, lv.z);
    rqs_eval(xv3.w, smem, k1,k2,k3,k4,k5,k6,k7, yv.w, lv.w);
    __stcs(&y4[i0 + 768],  yv);
    __stcs(&ld4[i0 + 768], lv);
}

// Tail: handles [start, n) scalar-wise; stream-ordered after main (no PDL),
// so prep is guaranteed complete. Not launched when n % 4096 == 0.
__global__ void rqs_tail_kernel(const float* __restrict__ x,
                                float* __restrict__ y,
                                float* __restrict__ ld,
                                int start, int n) {
    __shared__ __align__(16) float smem[112];
    if (threadIdx.x < 112) smem[threadIdx.x] = g_small[threadIdx.x];
    __syncthreads();
    for (int idx = start + blockIdx.x * blockDim.x + threadIdx.x; idx < n;
         idx += gridDim.x * blockDim.x) {
        float yy, ll;
        rqs_eval(x[idx], smem,
                 smem[96], smem[97], smem[98], smem[99],
                 smem[100], smem[101], smem[102], yy, ll);
        y[idx]  = yy;
        ld[idx] = ll;
    }
}

extern "C" void kernel_launch(void* const* d_in, const int* in_sizes, int n_in,
                              void* d_out, int out_size) {
    const float* x = (const float*)d_in[0];
    const float* p = (const float*)d_in[1];
    float* out = (float*)d_out;
    const int n = in_sizes[0];

    float* y_ptr  = out;       // out[0:N]  = y
    float* ld_ptr = out + n;   // out[N:2N] = logdet

    rqs_prep_kernel<<<1, 32>>>(p);

    const int elems_per_block = 4096;            // 256 thr * 4 * float4
    const int full_blocks = n / elems_per_block;
    if (full_blocks > 0) {
        cudaLaunchConfig_t cfg = {};
        cfg.gridDim  = dim3((unsigned)full_blocks, 1, 1);
        cfg.blockDim = dim3(256, 1, 1);
        cfg.dynamicSmemBytes = 0;
        cfg.stream = 0;
        cudaLaunchAttribute attrs[1];
        attrs[0].id = cudaLaunchAttributeProgrammaticStreamSerialization;
        attrs[0].val.programmaticStreamSerializationAllowed = 1;
        cfg.attrs = attrs;
        cfg.numAttrs = 1;
        cudaLaunchKernelEx(&cfg, rqs_main_kernel,
                           (const float4*)x, (float4*)y_ptr, (float4*)ld_ptr);
    }
    const int done = full_blocks * elems_per_block;
    if (done < n) {
        rqs_tail_kernel<<<4, 256>>>(x, y_ptr, ld_ptr, done, n);
    }
}